// round 10
// baseline (speedup 1.0000x reference)
#include <cuda_runtime.h>
#include <cuda_bf16.h>
#include <cstdint>

// Problem constants
#define Bn   64
#define Dn   512
#define Tn   512
#define Hn   1024
#define G4H  4096

// ---------------- scratch (device globals; no allocation allowed) ----------------
__device__ float g_xg[(size_t)Bn * Tn * G4H];              // (B, T, 4H)
__device__ __align__(16) __nv_bfloat16 g_hh[2][Bn * Hn];   // h hi, double-buffered by step
__device__ __align__(16) __nv_bfloat16 g_hl[2][Bn * Hn];   // h lo
__device__ unsigned int g_count;
__device__ unsigned int g_gen;

// ---------------- helpers ----------------
__device__ __forceinline__ uint32_t smem_u32(const void* p) {
    uint32_t a;
    asm("{ .reg .u64 t; cvta.to.shared.u64 t, %1; cvt.u32.u64 %0, t; }" : "=r"(a) : "l"(p));
    return a;
}
__device__ __forceinline__ float sigmf(float x) { return 1.0f / (1.0f + expf(-x)); }

// f32x2 (phase 1)
__device__ __forceinline__ void fma2(unsigned long long &d, unsigned long long a, unsigned long long b) {
    asm("fma.rn.f32x2 %0, %1, %2, %0;" : "+l"(d) : "l"(a), "l"(b));
}
__device__ __forceinline__ unsigned long long pack2(float x) {
    unsigned long long r;
    asm("mov.b64 %0, {%1, %1};" : "=l"(r) : "f"(x));
    return r;
}
__device__ __forceinline__ void unpack2(unsigned long long v, float &lo, float &hi) {
    asm("mov.b64 {%0, %1}, %2;" : "=f"(lo), "=f"(hi) : "l"(v));
}

// warp-level HMMA (sm_80+ PTX: compiles on plain sm_103 target)
__device__ __forceinline__ void mma_bf16(float* d, const uint32_t* a, const uint32_t* b) {
    asm volatile("mma.sync.aligned.m16n8k16.row.col.f32.bf16.bf16.f32 "
                 "{%0,%1,%2,%3}, {%4,%5,%6,%7}, {%8,%9}, {%0,%1,%2,%3};"
                 : "+f"(d[0]), "+f"(d[1]), "+f"(d[2]), "+f"(d[3])
                 : "r"(a[0]), "r"(a[1]), "r"(a[2]), "r"(a[3]), "r"(b[0]), "r"(b[1]));
}
__device__ __forceinline__ void ldsm4(uint32_t* r, uint32_t addr) {
    asm volatile("ldmatrix.sync.aligned.m8n8.x4.shared.b16 {%0,%1,%2,%3}, [%4];"
                 : "=r"(r[0]), "=r"(r[1]), "=r"(r[2]), "=r"(r[3]) : "r"(addr));
}

// =====================================================================
// init: zero h(0) hi/lo, out = b_out, reset grid barrier
// =====================================================================
__global__ void init_kernel(float* __restrict__ out, const float* __restrict__ bout) {
    int i = blockIdx.x * blockDim.x + threadIdx.x;   // 0..65535
    if (i < 32768) {
        ((unsigned*)g_hh)[i] = 0u;
        ((unsigned*)g_hl)[i] = 0u;
        out[i] = bout[0];
    }
    if (i == 0) { g_count = 0u; g_gen = 0u; }
}

// =====================================================================
// Phase 1: xg = x^T W_ih^T + b_ih + b_hh   (proven R2 kernel, unchanged)
// =====================================================================
#define P1_BM 128
#define P1_BN 128
#define P1_BK 16
#define P1_WPAD 132

__global__ __launch_bounds__(256, 2) void xg_gemm(
    const float* __restrict__ x, const float* __restrict__ Wih,
    const float* __restrict__ bih, const float* __restrict__ bhh)
{
    __shared__ float a_s[P1_BK][P1_BM];
    __shared__ float w_s[P1_BK][P1_WPAD];

    const int n0 = blockIdx.x * P1_BN;
    const int t0 = blockIdx.y * P1_BM;
    const int b  = blockIdx.z;
    const int tid = threadIdx.x;
    const int tx = tid & 15;
    const int ty = tid >> 4;

    unsigned long long acc[8][4];
#pragma unroll
    for (int m = 0; m < 8; m++)
#pragma unroll
        for (int p = 0; p < 4; p++) acc[m][p] = 0ull;

#pragma unroll
    for (int i = 0; i < 2; i++) {
        int f = tid + i * 256;
        int kk = f >> 5, mq = f & 31;
        float4 v = *(const float4*)&x[((size_t)(b * Dn + kk)) * Tn + t0 + mq * 4];
        *(float4*)&a_s[kk][mq * 4] = v;
    }
#pragma unroll
    for (int i = 0; i < 2; i++) {
        int f = tid + i * 256;
        int n = f >> 2, kq = f & 3;
        float4 v = *(const float4*)&Wih[((size_t)(n0 + n)) * Dn + kq * 4];
        w_s[kq * 4 + 0][n] = v.x; w_s[kq * 4 + 1][n] = v.y;
        w_s[kq * 4 + 2][n] = v.z; w_s[kq * 4 + 3][n] = v.w;
    }

    float4 pa[2], pw[2];
    const int NKT = Dn / P1_BK;
    for (int kt = 0; kt < NKT; kt++) {
        __syncthreads();
        if (kt < NKT - 1) {
            int k0 = (kt + 1) * P1_BK;
#pragma unroll
            for (int i = 0; i < 2; i++) {
                int f = tid + i * 256;
                int kk = f >> 5, mq = f & 31;
                pa[i] = *(const float4*)&x[((size_t)(b * Dn + k0 + kk)) * Tn + t0 + mq * 4];
            }
#pragma unroll
            for (int i = 0; i < 2; i++) {
                int f = tid + i * 256;
                int n = f >> 2, kq = f & 3;
                pw[i] = *(const float4*)&Wih[((size_t)(n0 + n)) * Dn + k0 + kq * 4];
            }
        }
#pragma unroll
        for (int kk = 0; kk < P1_BK; kk++) {
            float4 a0 = *(const float4*)&a_s[kk][ty * 8];
            float4 a1 = *(const float4*)&a_s[kk][ty * 8 + 4];
            ulonglong2 w0 = *(const ulonglong2*)&w_s[kk][tx * 8];
            ulonglong2 w1 = *(const ulonglong2*)&w_s[kk][tx * 8 + 4];
            float am[8] = {a0.x, a0.y, a0.z, a0.w, a1.x, a1.y, a1.z, a1.w};
#pragma unroll
            for (int m = 0; m < 8; m++) {
                unsigned long long ap = pack2(am[m]);
                fma2(acc[m][0], w0.x, ap);
                fma2(acc[m][1], w0.y, ap);
                fma2(acc[m][2], w1.x, ap);
                fma2(acc[m][3], w1.y, ap);
            }
        }
        __syncthreads();
        if (kt < NKT - 1) {
#pragma unroll
            for (int i = 0; i < 2; i++) {
                int f = tid + i * 256;
                int kk = f >> 5, mq = f & 31;
                *(float4*)&a_s[kk][mq * 4] = pa[i];
            }
#pragma unroll
            for (int i = 0; i < 2; i++) {
                int f = tid + i * 256;
                int n = f >> 2, kq = f & 3;
                w_s[kq * 4 + 0][n] = pw[i].x; w_s[kq * 4 + 1][n] = pw[i].y;
                w_s[kq * 4 + 2][n] = pw[i].z; w_s[kq * 4 + 3][n] = pw[i].w;
            }
        }
    }

    float bsum[8];
    {
        float4 u0 = *(const float4*)&bih[n0 + tx * 8];
        float4 u1 = *(const float4*)&bih[n0 + tx * 8 + 4];
        float4 v0 = *(const float4*)&bhh[n0 + tx * 8];
        float4 v1 = *(const float4*)&bhh[n0 + tx * 8 + 4];
        bsum[0] = u0.x + v0.x; bsum[1] = u0.y + v0.y; bsum[2] = u0.z + v0.z; bsum[3] = u0.w + v0.w;
        bsum[4] = u1.x + v1.x; bsum[5] = u1.y + v1.y; bsum[6] = u1.z + v1.z; bsum[7] = u1.w + v1.w;
    }
#pragma unroll
    for (int m = 0; m < 8; m++) {
        int t = t0 + ty * 8 + m;
        float o[8];
#pragma unroll
        for (int p = 0; p < 4; p++) {
            unpack2(acc[m][p], o[2 * p], o[2 * p + 1]);
            o[2 * p]     += bsum[2 * p];
            o[2 * p + 1] += bsum[2 * p + 1];
        }
        size_t base = ((size_t)b * Tn + t) * G4H + n0 + tx * 8;
        *(float4*)&g_xg[base]     = make_float4(o[0], o[1], o[2], o[3]);
        *(float4*)&g_xg[base + 4] = make_float4(o[4], o[5], o[6], o[7]);
    }
}

// =====================================================================
// Phase 2: persistent HMMA recurrence, A-operand direct from global.
// 128 CTAs x 128 thr (4 MMA warps, warp tile m16 x n32, K=1024, 3 passes).
// Weights resident in smem split-bf16, K-PERMUTED so that thread q's
// m16n8k16 A-fragment {2q,2q+1,2q+8,2q+9} == contiguous 8B of natural-order
// h: perm per 16-block: wpos 2q->orig 4q, 2q+1->4q+1, 2q+8->4q+2, 2q+9->4q+3.
// No smem staging of h, no syncthreads in K loop.
// =====================================================================
#define WPITCH 2064                  // 1032 bf16 per weight row; 129x16B banks
#define SM_WHI 0
#define SM_WLO 66048                 // 32*2064
#define SM_TOTAL2 132096

__global__ __launch_bounds__(128, 1) void lstm_mma(
    const float* __restrict__ Whh,
    const float* __restrict__ Wout,
    float* __restrict__ out)
{
    extern __shared__ char smem[];
    const uint32_t sb = smem_u32(smem);
    const int tid  = threadIdx.x;
    const int wid  = tid >> 5;
    const int lane = tid & 31;
    const int j0   = blockIdx.x * 8;
    const int nblocks = gridDim.x;

    // ---- pack resident split-bf16 weights, K-permuted ----
    // stored pos p holds orig k: (p & ~15) + 4*((p&7)>>1) + 2*((p>>3)&1) + (p&1)
    for (int it = 0; it < 256; it++) {
        int idx = it * 128 + tid;           // 0..32767
        int n = idx >> 10, p = idx & 1023;
        int g = n >> 3, cc = n & 7;
        int orig = (p & ~15) + 4 * ((p & 7) >> 1) + 2 * ((p >> 3) & 1) + (p & 1);
        float w = Whh[(size_t)(g * Hn + j0 + cc) * Hn + orig];
        __nv_bfloat16 hi = __float2bfloat16(w);
        __nv_bfloat16 lo = __float2bfloat16(w - __bfloat162float(hi));
        *(__nv_bfloat16*)(smem + SM_WHI + n * WPITCH + p * 2) = hi;
        *(__nv_bfloat16*)(smem + SM_WLO + n * WPITCH + p * 2) = lo;
    }
    __syncthreads();

    // geometry
    const int m0    = wid * 16;
    const int r     = m0 + (lane >> 2);      // A/D rows r, r+8
    const int q     = lane & 3;
    const int cc0   = q * 2;                 // D col pair
    // B ldsm4 per-lane address pieces: matrices [g0@k0, g0@k0+8, g1@k0, g1@k0+8]
    const int rowW  = (lane >> 4) * 8 + (lane & 7);     // gate-in-pair * 8 + row
    const int koff8 = ((lane >> 3) & 1) * 8;
    const uint32_t bh01 = sb + SM_WHI + rowW * WPITCH + koff8 * 2;
    const uint32_t bh23 = bh01 + 16 * WPITCH;
    const uint32_t bl01 = sb + SM_WLO + rowW * WPITCH + koff8 * 2;
    const uint32_t bl23 = bl01 + 16 * WPITCH;

    float wo_c[2];
    wo_c[0] = Wout[j0 + cc0];
    wo_c[1] = Wout[j0 + cc0 + 1];

    float cst[4] = {0.f, 0.f, 0.f, 0.f};

    for (int t = 0; t < Tn; t++) {
        const int rb = t & 1, wb = rb ^ 1;

        // xg prefetch: 2 rows x 4 gates x 2 cells
        float2 xf[2][4];
#pragma unroll
        for (int er = 0; er < 2; er++) {
            size_t base = ((size_t)(r + er * 8) * Tn + t) * G4H + j0 + cc0;
#pragma unroll
            for (int g = 0; g < 4; g++)
                xf[er][g] = *(const float2*)&g_xg[base + (size_t)g * Hn];
        }

        const __nv_bfloat16* __restrict__ Hh = g_hh[rb];
        const __nv_bfloat16* __restrict__ Hl = g_hl[rb];
        const __nv_bfloat16* hh_r  = Hh + (size_t)r * Hn + q * 4;
        const __nv_bfloat16* hh_r8 = hh_r + 8 * Hn;
        const __nv_bfloat16* hl_r  = Hl + (size_t)r * Hn + q * 4;
        const __nv_bfloat16* hl_r8 = hl_r + 8 * Hn;

        float acc[4][4];
#pragma unroll
        for (int g = 0; g < 4; g++)
#pragma unroll
            for (int p = 0; p < 4; p++) acc[g][p] = 0.f;

        // 8-deep register pipeline over 64 k-steps (16 elems each)
        uint2 pipe[8][4];
#pragma unroll
        for (int s = 0; s < 8; s++) {
            pipe[s][0] = *(const uint2*)&hh_r [s * 16];
            pipe[s][1] = *(const uint2*)&hh_r8[s * 16];
            pipe[s][2] = *(const uint2*)&hl_r [s * 16];
            pipe[s][3] = *(const uint2*)&hl_r8[s * 16];
        }

#pragma unroll
        for (int so = 0; so < 8; so++) {
#pragma unroll
            for (int si = 0; si < 8; si++) {
                const int s = so * 8 + si;
                const int slot = si;              // s & 7
                uint32_t ahi[4], alo[4];
                ahi[0] = pipe[slot][0].x; ahi[1] = pipe[slot][1].x;
                ahi[2] = pipe[slot][0].y; ahi[3] = pipe[slot][1].y;
                alo[0] = pipe[slot][2].x; alo[1] = pipe[slot][3].x;
                alo[2] = pipe[slot][2].y; alo[3] = pipe[slot][3].y;

                if (s < 56) {
                    pipe[slot][0] = *(const uint2*)&hh_r [(s + 8) * 16];
                    pipe[slot][1] = *(const uint2*)&hh_r8[(s + 8) * 16];
                    pipe[slot][2] = *(const uint2*)&hl_r [(s + 8) * 16];
                    pipe[slot][3] = *(const uint2*)&hl_r8[(s + 8) * 16];
                }

                uint32_t bh[4][2], bl[4][2];
                {
                    uint32_t rr[4];
                    ldsm4(rr, bh01 + s * 32);
                    bh[0][0] = rr[0]; bh[0][1] = rr[1]; bh[1][0] = rr[2]; bh[1][1] = rr[3];
                    ldsm4(rr, bh23 + s * 32);
                    bh[2][0] = rr[0]; bh[2][1] = rr[1]; bh[3][0] = rr[2]; bh[3][1] = rr[3];
                    ldsm4(rr, bl01 + s * 32);
                    bl[0][0] = rr[0]; bl[0][1] = rr[1]; bl[1][0] = rr[2]; bl[1][1] = rr[3];
                    ldsm4(rr, bl23 + s * 32);
                    bl[2][0] = rr[0]; bl[2][1] = rr[1]; bl[3][0] = rr[2]; bl[3][1] = rr[3];
                }
#pragma unroll
                for (int g = 0; g < 4; g++) {
                    mma_bf16(acc[g], ahi, bh[g]);
                    mma_bf16(acc[g], ahi, bl[g]);
                    mma_bf16(acc[g], alo, bh[g]);
                }
            }
        }

        // ---- epilogue ----
        float part[2];
#pragma unroll
        for (int er = 0; er < 2; er++) {
            int row = r + er * 8;
            float hv[2], pp = 0.f;
#pragma unroll
            for (int ec = 0; ec < 2; ec++) {
                int ci = er * 2 + ec;
                float xi = ec ? xf[er][0].y : xf[er][0].x;
                float xff = ec ? xf[er][1].y : xf[er][1].x;
                float xz = ec ? xf[er][2].y : xf[er][2].x;
                float xo = ec ? xf[er][3].y : xf[er][3].x;
                float gi = acc[0][ci] + xi;
                float gf = acc[1][ci] + xff;
                float gz = acc[2][ci] + xz;
                float go = acc[3][ci] + xo;
                float iv = sigmf(gi), fv = sigmf(gf), zv = tanhf(gz), ov = sigmf(go);
                cst[ci] = fv * cst[ci] + iv * zv;
                float h = ov * tanhf(cst[ci]);
                pp += h * wo_c[ec];
                hv[ec] = h;
            }
            union { __nv_bfloat16 h[2]; uint32_t u; } ph, pl;
            ph.h[0] = __float2bfloat16(hv[0]);
            ph.h[1] = __float2bfloat16(hv[1]);
            pl.h[0] = __float2bfloat16(hv[0] - __bfloat162float(ph.h[0]));
            pl.h[1] = __float2bfloat16(hv[1] - __bfloat162float(ph.h[1]));
            *(uint32_t*)&g_hh[wb][row * Hn + j0 + cc0] = ph.u;
            *(uint32_t*)&g_hl[wb][row * Hn + j0 + cc0] = pl.u;
            part[er] = pp;
        }
        part[0] += __shfl_xor_sync(0xffffffffu, part[0], 1);
        part[0] += __shfl_xor_sync(0xffffffffu, part[0], 2);
        part[1] += __shfl_xor_sync(0xffffffffu, part[1], 1);
        part[1] += __shfl_xor_sync(0xffffffffu, part[1], 2);
        if (q == 0) {
            atomicAdd(&out[(size_t)r * Tn + t], part[0]);
            atomicAdd(&out[(size_t)(r + 8) * Tn + t], part[1]);
        }

        // ---- grid barrier (128 CTAs, all resident) ----
        __threadfence();
        __syncthreads();
        if (tid == 0) {
            unsigned target = (unsigned)(t + 1);
            unsigned prev = atomicAdd(&g_count, 1u);
            if (prev == (unsigned)nblocks * target - 1u) {
                __threadfence();
                atomicExch(&g_gen, target);
            } else {
                while (*(volatile unsigned*)&g_gen < target) { __nanosleep(40); }
                __threadfence();
            }
        }
        __syncthreads();
    }
}

// =====================================================================
extern "C" void kernel_launch(void* const* d_in, const int* in_sizes, int n_in,
                              void* d_out, int out_size)
{
    const float* x    = (const float*)d_in[0];
    const float* Wih  = (const float*)d_in[1];
    const float* Whh  = (const float*)d_in[2];
    const float* bih  = (const float*)d_in[3];
    const float* bhh  = (const float*)d_in[4];
    const float* Wout = (const float*)d_in[5];
    const float* bout = (const float*)d_in[6];
    float* out = (float*)d_out;

    cudaFuncSetAttribute(lstm_mma, cudaFuncAttributeMaxDynamicSharedMemorySize, SM_TOTAL2);

    init_kernel<<<256, 256>>>(out, bout);
    xg_gemm<<<dim3(G4H / P1_BN, Tn / P1_BM, Bn), 256>>>(x, Wih, bih, bhh);
    lstm_mma<<<128, 128, SM_TOTAL2>>>(Whh, Wout, out);
}

// round 11
// speedup vs baseline: 1.4210x; 1.4210x over previous
#include <cuda_runtime.h>
#include <cuda_bf16.h>
#include <cuda_fp16.h>
#include <cstdint>

// Problem constants
#define Bn   64
#define Dn   512
#define Tn   512
#define Hn   1024
#define G4H  4096

// ---------------- scratch (device globals; no allocation allowed) ----------------
__device__ float g_xg[(size_t)Bn * Tn * G4H];          // (B, T, 4H)
__device__ __align__(16) __half g_hf[2][Bn * Hn];      // h fp16, double-buffered by step
__device__ unsigned int g_count;
__device__ unsigned int g_gen;

// ---------------- helpers ----------------
__device__ __forceinline__ uint32_t smem_u32(const void* p) {
    uint32_t a;
    asm("{ .reg .u64 t; cvta.to.shared.u64 t, %1; cvt.u32.u64 %0, t; }" : "=r"(a) : "l"(p));
    return a;
}
__device__ __forceinline__ float sigmf(float x) { return 1.0f / (1.0f + expf(-x)); }

// f32x2 (phase 1)
__device__ __forceinline__ void fma2(unsigned long long &d, unsigned long long a, unsigned long long b) {
    asm("fma.rn.f32x2 %0, %1, %2, %0;" : "+l"(d) : "l"(a), "l"(b));
}
__device__ __forceinline__ unsigned long long pack2(float x) {
    unsigned long long r;
    asm("mov.b64 %0, {%1, %1};" : "=l"(r) : "f"(x));
    return r;
}
__device__ __forceinline__ void unpack2(unsigned long long v, float &lo, float &hi) {
    asm("mov.b64 {%0, %1}, %2;" : "=f"(lo), "=f"(hi) : "l"(v));
}

// warp-level HMMA fp16 (sm_80+ PTX: compiles on plain sm_103 target)
__device__ __forceinline__ void mma_f16(float* d, const uint32_t* a, const uint32_t* b) {
    asm volatile("mma.sync.aligned.m16n8k16.row.col.f32.f16.f16.f32 "
                 "{%0,%1,%2,%3}, {%4,%5,%6,%7}, {%8,%9}, {%0,%1,%2,%3};"
                 : "+f"(d[0]), "+f"(d[1]), "+f"(d[2]), "+f"(d[3])
                 : "r"(a[0]), "r"(a[1]), "r"(a[2]), "r"(a[3]), "r"(b[0]), "r"(b[1]));
}
__device__ __forceinline__ void ldsm4(uint32_t* r, uint32_t addr) {
    asm volatile("ldmatrix.sync.aligned.m8n8.x4.shared.b16 {%0,%1,%2,%3}, [%4];"
                 : "=r"(r[0]), "=r"(r[1]), "=r"(r[2]), "=r"(r[3]) : "r"(addr));
}

// =====================================================================
// init: zero h(0), out = b_out, reset grid barrier
// =====================================================================
__global__ void init_kernel(float* __restrict__ out, const float* __restrict__ bout) {
    int i = blockIdx.x * blockDim.x + threadIdx.x;   // 0..65535
    if (i < 32768) {
        ((unsigned*)g_hf)[i] = 0u;                   // g_hf[0]: 64K halves = 32768 words
        out[i] = bout[0];
    }
    if (i == 0) { g_count = 0u; g_gen = 0u; }
}

// =====================================================================
// Phase 1: xg = x^T W_ih^T + b_ih + b_hh   (proven R2 kernel, unchanged)
// =====================================================================
#define P1_BM 128
#define P1_BN 128
#define P1_BK 16
#define P1_WPAD 132

__global__ __launch_bounds__(256, 2) void xg_gemm(
    const float* __restrict__ x, const float* __restrict__ Wih,
    const float* __restrict__ bih, const float* __restrict__ bhh)
{
    __shared__ float a_s[P1_BK][P1_BM];
    __shared__ float w_s[P1_BK][P1_WPAD];

    const int n0 = blockIdx.x * P1_BN;
    const int t0 = blockIdx.y * P1_BM;
    const int b  = blockIdx.z;
    const int tid = threadIdx.x;
    const int tx = tid & 15;
    const int ty = tid >> 4;

    unsigned long long acc[8][4];
#pragma unroll
    for (int m = 0; m < 8; m++)
#pragma unroll
        for (int p = 0; p < 4; p++) acc[m][p] = 0ull;

#pragma unroll
    for (int i = 0; i < 2; i++) {
        int f = tid + i * 256;
        int kk = f >> 5, mq = f & 31;
        float4 v = *(const float4*)&x[((size_t)(b * Dn + kk)) * Tn + t0 + mq * 4];
        *(float4*)&a_s[kk][mq * 4] = v;
    }
#pragma unroll
    for (int i = 0; i < 2; i++) {
        int f = tid + i * 256;
        int n = f >> 2, kq = f & 3;
        float4 v = *(const float4*)&Wih[((size_t)(n0 + n)) * Dn + kq * 4];
        w_s[kq * 4 + 0][n] = v.x; w_s[kq * 4 + 1][n] = v.y;
        w_s[kq * 4 + 2][n] = v.z; w_s[kq * 4 + 3][n] = v.w;
    }

    float4 pa[2], pw[2];
    const int NKT = Dn / P1_BK;
    for (int kt = 0; kt < NKT; kt++) {
        __syncthreads();
        if (kt < NKT - 1) {
            int k0 = (kt + 1) * P1_BK;
#pragma unroll
            for (int i = 0; i < 2; i++) {
                int f = tid + i * 256;
                int kk = f >> 5, mq = f & 31;
                pa[i] = *(const float4*)&x[((size_t)(b * Dn + k0 + kk)) * Tn + t0 + mq * 4];
            }
#pragma unroll
            for (int i = 0; i < 2; i++) {
                int f = tid + i * 256;
                int n = f >> 2, kq = f & 3;
                pw[i] = *(const float4*)&Wih[((size_t)(n0 + n)) * Dn + k0 + kq * 4];
            }
        }
#pragma unroll
        for (int kk = 0; kk < P1_BK; kk++) {
            float4 a0 = *(const float4*)&a_s[kk][ty * 8];
            float4 a1 = *(const float4*)&a_s[kk][ty * 8 + 4];
            ulonglong2 w0 = *(const ulonglong2*)&w_s[kk][tx * 8];
            ulonglong2 w1 = *(const ulonglong2*)&w_s[kk][tx * 8 + 4];
            float am[8] = {a0.x, a0.y, a0.z, a0.w, a1.x, a1.y, a1.z, a1.w};
#pragma unroll
            for (int m = 0; m < 8; m++) {
                unsigned long long ap = pack2(am[m]);
                fma2(acc[m][0], w0.x, ap);
                fma2(acc[m][1], w0.y, ap);
                fma2(acc[m][2], w1.x, ap);
                fma2(acc[m][3], w1.y, ap);
            }
        }
        __syncthreads();
        if (kt < NKT - 1) {
#pragma unroll
            for (int i = 0; i < 2; i++) {
                int f = tid + i * 256;
                int kk = f >> 5, mq = f & 31;
                *(float4*)&a_s[kk][mq * 4] = pa[i];
            }
#pragma unroll
            for (int i = 0; i < 2; i++) {
                int f = tid + i * 256;
                int n = f >> 2, kq = f & 3;
                w_s[kq * 4 + 0][n] = pw[i].x; w_s[kq * 4 + 1][n] = pw[i].y;
                w_s[kq * 4 + 2][n] = pw[i].z; w_s[kq * 4 + 3][n] = pw[i].w;
            }
        }
    }

    float bsum[8];
    {
        float4 u0 = *(const float4*)&bih[n0 + tx * 8];
        float4 u1 = *(const float4*)&bih[n0 + tx * 8 + 4];
        float4 v0 = *(const float4*)&bhh[n0 + tx * 8];
        float4 v1 = *(const float4*)&bhh[n0 + tx * 8 + 4];
        bsum[0] = u0.x + v0.x; bsum[1] = u0.y + v0.y; bsum[2] = u0.z + v0.z; bsum[3] = u0.w + v0.w;
        bsum[4] = u1.x + v1.x; bsum[5] = u1.y + v1.y; bsum[6] = u1.z + v1.z; bsum[7] = u1.w + v1.w;
    }
#pragma unroll
    for (int m = 0; m < 8; m++) {
        int t = t0 + ty * 8 + m;
        float o[8];
#pragma unroll
        for (int p = 0; p < 4; p++) {
            unpack2(acc[m][p], o[2 * p], o[2 * p + 1]);
            o[2 * p]     += bsum[2 * p];
            o[2 * p + 1] += bsum[2 * p + 1];
        }
        size_t base = ((size_t)b * Tn + t) * G4H + n0 + tx * 8;
        *(float4*)&g_xg[base]     = make_float4(o[0], o[1], o[2], o[3]);
        *(float4*)&g_xg[base + 4] = make_float4(o[4], o[5], o[6], o[7]);
    }
}

// =====================================================================
// Phase 2: persistent HMMA recurrence, fp16 single-pass.
// 128 CTAs x 256 thr. CTA owns 8 h-cols (32 Whh rows, 4 gates), resident
// in smem as fp16 [n][k], pitch 2064B. Warps 0-3: MMA (m16 x n32, K=1024).
// Warps 4-7: stage h fp16 512-k chunks global->smem, double buffered
// (2 chunks/step => 2 sync points in K loop).
// =====================================================================
#define WPITCH 2064                   // 1032 fp16; 129x16B
#define APITCH 1040                   // 520 fp16 (512 k + pad); 65x16B
#define SM_W   0
#define SM_AB  66048                  // 32*2064
#define ABUFSZ 66560                  // 64*1040
#define SM_TOTAL2 (66048 + 2*66560)   // 199168

__global__ __launch_bounds__(256, 1) void lstm_mma(
    const float* __restrict__ Whh,
    const float* __restrict__ Wout,
    float* __restrict__ out)
{
    extern __shared__ char smem[];
    const uint32_t sb = smem_u32(smem);
    const int tid  = threadIdx.x;
    const int wid  = tid >> 5;
    const int lane = tid & 31;
    const int j0   = blockIdx.x * 8;
    const int nblocks = gridDim.x;

    // ---- pack resident fp16 weights: w[n][k], n = g*8+cc ----
    for (int it = 0; it < 128; it++) {
        int idx = it * 256 + tid;           // 0..32767
        int n = idx >> 10, k = idx & 1023;
        int g = n >> 3, cc = n & 7;
        float w = Whh[(size_t)(g * Hn + j0 + cc) * Hn + k];
        *(__half*)(smem + SM_W + n * WPITCH + k * 2) = __float2half(w);
    }
    __syncthreads();

    // compute-warp geometry (wid < 4)
    const int m0    = wid * 16;
    const int r     = m0 + (lane >> 2);      // D rows r, r+8
    const int q     = lane & 3;
    const int cc0   = q * 2;                 // D col pair
    // A ldmatrix address pieces
    const int am   = lane >> 3;
    const int arow = (lane & 7) + (am & 1) * 8;
    const int acol = (am >> 1) * 8;
    // B ldsm4 (gate-paired, R10-proven): matrices [gp0@k0, gp0@k0+8, gp1@k0, gp1@k0+8]
    const int rowW  = (lane >> 4) * 8 + (lane & 7);
    const int koff8 = ((lane >> 3) & 1) * 8;
    const uint32_t b01 = sb + SM_W + rowW * WPITCH + koff8 * 2;           // gates 0,1
    const uint32_t b23 = b01 + 16 * WPITCH;                               // gates 2,3

    float wo_c[2];
    wo_c[0] = Wout[j0 + cc0];
    wo_c[1] = Wout[j0 + cc0 + 1];

    float cst[4] = {0.f, 0.f, 0.f, 0.f};

    for (int t = 0; t < Tn; t++) {
        const int rb = t & 1, wb = rb ^ 1;

        float2 xf[2][4];
        float acc[4][4];

        if (wid < 4) {
            // xg prefetch: 2 rows x 4 gates x 2 cells
#pragma unroll
            for (int er = 0; er < 2; er++) {
                size_t base = ((size_t)(r + er * 8) * Tn + t) * G4H + j0 + cc0;
#pragma unroll
                for (int g = 0; g < 4; g++)
                    xf[er][g] = *(const float2*)&g_xg[base + (size_t)g * Hn];
            }
#pragma unroll
            for (int g = 0; g < 4; g++)
#pragma unroll
                for (int p = 0; p < 4; p++) acc[g][p] = 0.f;
        } else {
            // stage chunk 0 (k 0..511) into buf0: 64 rows x 1024B
            int sid = tid - 128;
#pragma unroll
            for (int i = 0; i < 32; i++) {
                int id = i * 128 + sid;              // 0..4095
                int row = id >> 6, qq = id & 63;
                *(uint4*)(smem + SM_AB + row * APITCH + qq * 16) =
                    *(const uint4*)&g_hf[rb][row * Hn + qq * 8];
            }
        }
        __syncthreads();

#pragma unroll 1
        for (int c = 0; c < 2; c++) {
            if (wid >= 4) {
                if (c == 0) {
                    // stage chunk 1 into buf1 while chunk 0 is consumed
                    int sid = tid - 128;
#pragma unroll
                    for (int i = 0; i < 32; i++) {
                        int id = i * 128 + sid;
                        int row = id >> 6, qq = id & 63;
                        *(uint4*)(smem + SM_AB + ABUFSZ + row * APITCH + qq * 16) =
                            *(const uint4*)&g_hf[rb][row * Hn + 512 + qq * 8];
                    }
                }
            } else {
                const uint32_t abuf = sb + SM_AB + c * ABUFSZ
                                    + (m0 + arow) * APITCH + acol * 2;
                const uint32_t bk0 = c * 512;
#pragma unroll
                for (int ks = 0; ks < 32; ks++) {
                    uint32_t a[4];
                    ldsm4(a, abuf + ks * 32);
                    uint32_t bf[4][2];
                    {
                        uint32_t rr[4];
                        ldsm4(rr, b01 + (bk0 + ks * 16) * 2);
                        bf[0][0] = rr[0]; bf[0][1] = rr[1];
                        bf[1][0] = rr[2]; bf[1][1] = rr[3];
                        ldsm4(rr, b23 + (bk0 + ks * 16) * 2);
                        bf[2][0] = rr[0]; bf[2][1] = rr[1];
                        bf[3][0] = rr[2]; bf[3][1] = rr[3];
                    }
#pragma unroll
                    for (int g = 0; g < 4; g++)
                        mma_f16(acc[g], a, bf[g]);
                }
            }
            __syncthreads();
        }

        // ---- epilogue (compute warps) ----
        if (wid < 4) {
            float part[2];
#pragma unroll
            for (int er = 0; er < 2; er++) {
                int row = r + er * 8;
                float hv[2], pp = 0.f;
#pragma unroll
                for (int ec = 0; ec < 2; ec++) {
                    int ci = er * 2 + ec;
                    float xi = ec ? xf[er][0].y : xf[er][0].x;
                    float xff = ec ? xf[er][1].y : xf[er][1].x;
                    float xz = ec ? xf[er][2].y : xf[er][2].x;
                    float xo = ec ? xf[er][3].y : xf[er][3].x;
                    float gi = acc[0][ci] + xi;
                    float gf = acc[1][ci] + xff;
                    float gz = acc[2][ci] + xz;
                    float go = acc[3][ci] + xo;
                    float iv = sigmf(gi), fv = sigmf(gf), zv = tanhf(gz), ov = sigmf(go);
                    cst[ci] = fv * cst[ci] + iv * zv;
                    float h = ov * tanhf(cst[ci]);
                    pp += h * wo_c[ec];
                    hv[ec] = h;
                }
                union { __half h[2]; uint32_t u; } ph;
                ph.h[0] = __float2half(hv[0]);
                ph.h[1] = __float2half(hv[1]);
                *(uint32_t*)&g_hf[wb][row * Hn + j0 + cc0] = ph.u;
                part[er] = pp;
            }
            part[0] += __shfl_xor_sync(0xffffffffu, part[0], 1);
            part[0] += __shfl_xor_sync(0xffffffffu, part[0], 2);
            part[1] += __shfl_xor_sync(0xffffffffu, part[1], 1);
            part[1] += __shfl_xor_sync(0xffffffffu, part[1], 2);
            if (q == 0) {
                atomicAdd(&out[(size_t)r * Tn + t], part[0]);
                atomicAdd(&out[(size_t)(r + 8) * Tn + t], part[1]);
            }
        }

        // ---- grid barrier (128 CTAs, all resident) ----
        __threadfence();
        __syncthreads();
        if (tid == 0) {
            unsigned target = (unsigned)(t + 1);
            unsigned prev = atomicAdd(&g_count, 1u);
            if (prev == (unsigned)nblocks * target - 1u) {
                __threadfence();
                atomicExch(&g_gen, target);
            } else {
                while (*(volatile unsigned*)&g_gen < target) { __nanosleep(40); }
                __threadfence();
            }
        }
        __syncthreads();
    }
}

// =====================================================================
extern "C" void kernel_launch(void* const* d_in, const int* in_sizes, int n_in,
                              void* d_out, int out_size)
{
    const float* x    = (const float*)d_in[0];
    const float* Wih  = (const float*)d_in[1];
    const float* Whh  = (const float*)d_in[2];
    const float* bih  = (const float*)d_in[3];
    const float* bhh  = (const float*)d_in[4];
    const float* Wout = (const float*)d_in[5];
    const float* bout = (const float*)d_in[6];
    float* out = (float*)d_out;

    cudaFuncSetAttribute(lstm_mma, cudaFuncAttributeMaxDynamicSharedMemorySize, SM_TOTAL2);

    init_kernel<<<256, 256>>>(out, bout);
    xg_gemm<<<dim3(G4H / P1_BN, Tn / P1_BM, Bn), 256>>>(x, Wih, bih, bhh);
    lstm_mma<<<128, 256, SM_TOTAL2>>>(Whh, Wout, out);
}

// round 14
// speedup vs baseline: 2.1384x; 1.5048x over previous
#include <cuda_runtime.h>
#include <cuda_bf16.h>
#include <cuda_fp16.h>
#include <cstdint>

// Problem constants
#define Bn   64
#define Dn   512
#define Tn   512
#define Hn   1024
#define G4H  4096

// ---------------- scratch (device globals; no allocation allowed) ----------------
__device__ float g_xg[(size_t)Bn * Tn * G4H];          // (B, T, 4H)
__device__ __align__(16) __half g_xh[(size_t)Bn * Dn * Tn];   // x fp16 (B, D, T)
__device__ __align__(16) __half g_wh[(size_t)G4H * Dn];       // W_ih fp16 (4H, D)
__device__ __align__(16) __half g_hf[2][Bn * Hn];      // h fp16, double-buffered by step
__device__ unsigned int g_count;
__device__ unsigned int g_gen;

// ---------------- helpers ----------------
__device__ __forceinline__ uint32_t smem_u32(const void* p) {
    uint32_t a;
    asm("{ .reg .u64 t; cvta.to.shared.u64 t, %1; cvt.u32.u64 %0, t; }" : "=r"(a) : "l"(p));
    return a;
}
__device__ __forceinline__ float sigmf(float x) { return 1.0f / (1.0f + expf(-x)); }

// warp-level HMMA fp16 (sm_80+ PTX: compiles on plain sm_103 target)
__device__ __forceinline__ void mma_f16(float* d, const uint32_t* a, const uint32_t* b) {
    asm volatile("mma.sync.aligned.m16n8k16.row.col.f32.f16.f16.f32 "
                 "{%0,%1,%2,%3}, {%4,%5,%6,%7}, {%8,%9}, {%0,%1,%2,%3};"
                 : "+f"(d[0]), "+f"(d[1]), "+f"(d[2]), "+f"(d[3])
                 : "r"(a[0]), "r"(a[1]), "r"(a[2]), "r"(a[3]), "r"(b[0]), "r"(b[1]));
}
__device__ __forceinline__ void ldsm4(uint32_t* r, uint32_t addr) {
    asm volatile("ldmatrix.sync.aligned.m8n8.x4.shared.b16 {%0,%1,%2,%3}, [%4];"
                 : "=r"(r[0]), "=r"(r[1]), "=r"(r[2]), "=r"(r[3]) : "r"(addr));
}
__device__ __forceinline__ void ldsm4t(uint32_t* r, uint32_t addr) {
    asm volatile("ldmatrix.sync.aligned.m8n8.x4.trans.shared.b16 {%0,%1,%2,%3}, [%4];"
                 : "=r"(r[0]), "=r"(r[1]), "=r"(r[2]), "=r"(r[3]) : "r"(addr));
}

// =====================================================================
// init: zero h(0), out = b_out, reset grid barrier
// =====================================================================
__global__ void init_kernel(float* __restrict__ out, const float* __restrict__ bout) {
    int i = blockIdx.x * blockDim.x + threadIdx.x;   // 0..65535
    if (i < 32768) {
        ((unsigned*)g_hf)[i] = 0u;
        out[i] = bout[0];
    }
    if (i == 0) { g_count = 0u; g_gen = 0u; }
}

// =====================================================================
// convert: x (B,D,T) fp32 -> g_xh fp16 ; W_ih (4H,D) fp32 -> g_wh fp16
// =====================================================================
#define NXQ ((Bn * Dn * Tn) / 4)      // 4194304
#define NWQ ((G4H * Dn) / 4)          // 524288
__global__ void convert_kernel(const float* __restrict__ x, const float* __restrict__ Wih) {
    int i = blockIdx.x * blockDim.x + threadIdx.x;
    if (i < NXQ) {
        float4 v = *(const float4*)&x[(size_t)i * 4];
        __half2 a = __floats2half2_rn(v.x, v.y);
        __half2 b = __floats2half2_rn(v.z, v.w);
        *(uint2*)&g_xh[(size_t)i * 4] = make_uint2(*(uint32_t*)&a, *(uint32_t*)&b);
    } else if (i < NXQ + NWQ) {
        int j = i - NXQ;
        float4 v = *(const float4*)&Wih[(size_t)j * 4];
        __half2 a = __floats2half2_rn(v.x, v.y);
        __half2 b = __floats2half2_rn(v.z, v.w);
        *(uint2*)&g_wh[(size_t)j * 4] = make_uint2(*(uint32_t*)&a, *(uint32_t*)&b);
    }
}

// =====================================================================
// Phase 1: xg[b][t][n] = sum_d xh[b][d][t] * wh[n][d] + b_ih[n] + b_hh[n]
// HMMA fp16 GEMM. Block tile 128(t) x 128(n) x BK64, 256 thr, 8 warps 4m x 2n,
// warp tile m32 x n64. A^T staged [k][m] (trans-ldsm), B staged [n][k].
// =====================================================================
#define G_BM 128
#define G_BN 128
#define G_BK 64
#define G_APITCH 272                  // (128+8) fp16 bytes pitch: 17x16B
#define G_BPITCH 144                  // (64+8) fp16 bytes: 9x16B
#define G_ASZ (G_BK * G_APITCH)       // 17408
#define G_BSZ (G_BN * G_BPITCH)       // 18432
#define G_SMEM (2 * (G_ASZ + G_BSZ)) // 71680

__global__ __launch_bounds__(256, 1) void xg_hmma(
    const float* __restrict__ bih, const float* __restrict__ bhh)
{
    extern __shared__ char smem[];
    const uint32_t sb = smem_u32(smem);
    const int tid  = threadIdx.x;
    const int wid  = tid >> 5;
    const int lane = tid & 31;

    const int n0 = blockIdx.x * G_BN;
    const int t0 = blockIdx.y * G_BM;
    const int b  = blockIdx.z;

    const int mo = (wid & 3) * 32;      // warp m offset
    const int no = (wid >> 2) * 64;     // warp n offset

    // A trans-ldsm per-lane pieces: matrices (m0k0, m8k0, m0k8, m8k8)
    const int krow = (lane & 7) + ((lane >> 4) & 1) * 8;
    const int mcol = ((lane >> 3) & 1) * 8;
    // B ldsm per-lane pieces (phase-2-proven pairing): per n16 pair
    const int rowN  = (lane >> 4) * 8 + (lane & 7);
    const int koff8 = ((lane >> 3) & 1) * 8;

    // global load indexing
    const int arow = tid >> 4;                 // A: k-row 0..15 (x4 -> 64)
    const int acol8 = tid & 15;                // m col8 0..15
    const int brow = tid >> 3;                 // B: n-row 0..31 (x4 -> 128)
    const int bcol8 = tid & 7;                 // k col8 0..7

    const __half* __restrict__ XH = g_xh + ((size_t)b * Dn) * Tn + t0;
    const __half* __restrict__ WH = g_wh + (size_t)n0 * Dn;

    float acc[2][8][4];
#pragma unroll
    for (int f = 0; f < 2; f++)
#pragma unroll
        for (int p = 0; p < 8; p++)
#pragma unroll
            for (int e = 0; e < 4; e++) acc[f][p][e] = 0.f;

    // ---- initial tile (kt=0) into buffer 0 ----
    {
#pragma unroll
        for (int i = 0; i < 4; i++) {
            int kk = arow + i * 16;
            uint4 v = *(const uint4*)&XH[(size_t)kk * Tn + acol8 * 8];
            *(uint4*)(smem + 0 + kk * G_APITCH + acol8 * 16) = v;
        }
#pragma unroll
        for (int i = 0; i < 4; i++) {
            int nn = brow + i * 32;
            uint4 v = *(const uint4*)&WH[(size_t)nn * Dn + bcol8 * 8];
            *(uint4*)(smem + 2 * G_ASZ + nn * G_BPITCH + bcol8 * 16) = v;
        }
    }
    __syncthreads();

    const int NKT = Dn / G_BK;         // 8
#pragma unroll 1
    for (int kt = 0; kt < NKT; kt++) {
        // prefetch next tile into regs
        uint4 pa[4], pb[4];
        if (kt < NKT - 1) {
            int k0 = (kt + 1) * G_BK;
#pragma unroll
            for (int i = 0; i < 4; i++) {
                int kk = arow + i * 16;
                pa[i] = *(const uint4*)&XH[(size_t)(k0 + kk) * Tn + acol8 * 8];
            }
#pragma unroll
            for (int i = 0; i < 4; i++) {
                int nn = brow + i * 32;
                pb[i] = *(const uint4*)&WH[(size_t)nn * Dn + k0 + bcol8 * 8];
            }
        }

        // compute from buffer kt&1
        const uint32_t abuf = sb + (kt & 1) * G_ASZ;
        const uint32_t bbuf = sb + 2 * G_ASZ + (kt & 1) * G_BSZ;
#pragma unroll
        for (int s = 0; s < 4; s++) {
            uint32_t af[2][4];
#pragma unroll
            for (int f = 0; f < 2; f++)
                ldsm4t(af[f], abuf + (s * 16 + krow) * G_APITCH + (mo + f * 16 + mcol) * 2);
            uint32_t bf[8][2];
#pragma unroll
            for (int p = 0; p < 4; p++) {
                uint32_t rr[4];
                ldsm4(rr, bbuf + (no + p * 16 + rowN) * G_BPITCH + (s * 16 + koff8) * 2);
                bf[p * 2][0] = rr[0]; bf[p * 2][1] = rr[1];
                bf[p * 2 + 1][0] = rr[2]; bf[p * 2 + 1][1] = rr[3];
            }
#pragma unroll
            for (int f = 0; f < 2; f++)
#pragma unroll
                for (int p = 0; p < 8; p++)
                    mma_f16(acc[f][p], af[f], bf[p]);
        }

        // store prefetched tile into other buffer
        if (kt < NKT - 1) {
            const uint32_t oa = (kt + 1) & 1;
            char* ab = smem + oa * G_ASZ;
            char* bb = smem + 2 * G_ASZ + oa * G_BSZ;
#pragma unroll
            for (int i = 0; i < 4; i++) {
                int kk = arow + i * 16;
                *(uint4*)(ab + kk * G_APITCH + acol8 * 16) = pa[i];
            }
#pragma unroll
            for (int i = 0; i < 4; i++) {
                int nn = brow + i * 32;
                *(uint4*)(bb + nn * G_BPITCH + bcol8 * 16) = pb[i];
            }
        }
        __syncthreads();
    }

    // ---- epilogue: add biases (fp32) and store to g_xg ----
    const int qq = lane & 3;
#pragma unroll
    for (int p = 0; p < 8; p++) {
        int n = n0 + no + (p >> 1) * 16 + (p & 1) * 8 + qq * 2;
        float2 bsv;
        bsv.x = bih[n] + bhh[n];
        bsv.y = bih[n + 1] + bhh[n + 1];
#pragma unroll
        for (int f = 0; f < 2; f++) {
            int r0 = t0 + mo + f * 16 + (lane >> 2);
            size_t base0 = ((size_t)b * Tn + r0) * G4H + n;
            size_t base1 = ((size_t)b * Tn + r0 + 8) * G4H + n;
            *(float2*)&g_xg[base0] = make_float2(acc[f][p][0] + bsv.x, acc[f][p][1] + bsv.y);
            *(float2*)&g_xg[base1] = make_float2(acc[f][p][2] + bsv.x, acc[f][p][3] + bsv.y);
        }
    }
}

// =====================================================================
// Phase 2: persistent HMMA recurrence, fp16 single-pass (R11-proven).
// 128 CTAs x 256 thr. Warps 0-3: MMA (m16 x n32, K=1024).
// Warps 4-7: stage h fp16 512-k chunks global->smem, double buffered.
// =====================================================================
#define WPITCH 2064                   // 1032 fp16; 129x16B
#define APITCH 1040                   // 520 fp16 (512 k + pad); 65x16B
#define SM_W   0
#define SM_AB  66048                  // 32*2064
#define ABUFSZ 66560                  // 64*1040
#define SM_TOTAL2 (66048 + 2*66560)   // 199168

__global__ __launch_bounds__(256, 1) void lstm_mma(
    const float* __restrict__ Whh,
    const float* __restrict__ Wout,
    float* __restrict__ out)
{
    extern __shared__ char smem[];
    const uint32_t sb = smem_u32(smem);
    const int tid  = threadIdx.x;
    const int wid  = tid >> 5;
    const int lane = tid & 31;
    const int j0   = blockIdx.x * 8;
    const int nblocks = gridDim.x;

    // ---- pack resident fp16 weights: w[n][k], n = g*8+cc ----
    for (int it = 0; it < 128; it++) {
        int idx = it * 256 + tid;           // 0..32767
        int n = idx >> 10, k = idx & 1023;
        int g = n >> 3, cc = n & 7;
        float w = Whh[(size_t)(g * Hn + j0 + cc) * Hn + k];
        *(__half*)(smem + SM_W + n * WPITCH + k * 2) = __float2half(w);
    }
    __syncthreads();

    // compute-warp geometry (wid < 4)
    const int m0    = wid * 16;
    const int r     = m0 + (lane >> 2);      // D rows r, r+8
    const int q     = lane & 3;
    const int cc0   = q * 2;                 // D col pair
    // A ldmatrix address pieces
    const int am   = lane >> 3;
    const int arow = (lane & 7) + (am & 1) * 8;
    const int acol = (am >> 1) * 8;
    // B ldsm4 (gate-paired): matrices [gp0@k0, gp0@k0+8, gp1@k0, gp1@k0+8]
    const int rowW  = (lane >> 4) * 8 + (lane & 7);
    const int koff8 = ((lane >> 3) & 1) * 8;
    const uint32_t b01 = sb + SM_W + rowW * WPITCH + koff8 * 2;           // gates 0,1
    const uint32_t b23 = b01 + 16 * WPITCH;                               // gates 2,3

    float wo_c[2];
    wo_c[0] = Wout[j0 + cc0];
    wo_c[1] = Wout[j0 + cc0 + 1];

    float cst[4] = {0.f, 0.f, 0.f, 0.f};

    for (int t = 0; t < Tn; t++) {
        const int rb = t & 1, wb = rb ^ 1;

        float2 xf[2][4];
        float acc[4][4];

        if (wid < 4) {
#pragma unroll
            for (int er = 0; er < 2; er++) {
                size_t base = ((size_t)(r + er * 8) * Tn + t) * G4H + j0 + cc0;
#pragma unroll
                for (int g = 0; g < 4; g++)
                    xf[er][g] = *(const float2*)&g_xg[base + (size_t)g * Hn];
            }
#pragma unroll
            for (int g = 0; g < 4; g++)
#pragma unroll
                for (int p = 0; p < 4; p++) acc[g][p] = 0.f;
        } else {
            int sid = tid - 128;
#pragma unroll
            for (int i = 0; i < 32; i++) {
                int id = i * 128 + sid;              // 0..4095
                int row = id >> 6, qq = id & 63;
                *(uint4*)(smem + SM_AB + row * APITCH + qq * 16) =
                    *(const uint4*)&g_hf[rb][row * Hn + qq * 8];
            }
        }
        __syncthreads();

#pragma unroll 1
        for (int c = 0; c < 2; c++) {
            if (wid >= 4) {
                if (c == 0) {
                    int sid = tid - 128;
#pragma unroll
                    for (int i = 0; i < 32; i++) {
                        int id = i * 128 + sid;
                        int row = id >> 6, qq = id & 63;
                        *(uint4*)(smem + SM_AB + ABUFSZ + row * APITCH + qq * 16) =
                            *(const uint4*)&g_hf[rb][row * Hn + 512 + qq * 8];
                    }
                }
            } else {
                const uint32_t abuf = sb + SM_AB + c * ABUFSZ
                                    + (m0 + arow) * APITCH + acol * 2;
                const uint32_t bk0 = c * 512;
#pragma unroll
                for (int ks = 0; ks < 32; ks++) {
                    uint32_t a[4];
                    ldsm4(a, abuf + ks * 32);
                    uint32_t bf[4][2];
                    {
                        uint32_t rr[4];
                        ldsm4(rr, b01 + (bk0 + ks * 16) * 2);
                        bf[0][0] = rr[0]; bf[0][1] = rr[1];
                        bf[1][0] = rr[2]; bf[1][1] = rr[3];
                        ldsm4(rr, b23 + (bk0 + ks * 16) * 2);
                        bf[2][0] = rr[0]; bf[2][1] = rr[1];
                        bf[3][0] = rr[2]; bf[3][1] = rr[3];
                    }
#pragma unroll
                    for (int g = 0; g < 4; g++)
                        mma_f16(acc[g], a, bf[g]);
                }
            }
            __syncthreads();
        }

        // ---- epilogue (compute warps) ----
        if (wid < 4) {
            float part[2];
#pragma unroll
            for (int er = 0; er < 2; er++) {
                int row = r + er * 8;
                float hv[2], pp = 0.f;
#pragma unroll
                for (int ec = 0; ec < 2; ec++) {
                    int ci = er * 2 + ec;
                    float xi = ec ? xf[er][0].y : xf[er][0].x;
                    float xff = ec ? xf[er][1].y : xf[er][1].x;
                    float xz = ec ? xf[er][2].y : xf[er][2].x;
                    float xo = ec ? xf[er][3].y : xf[er][3].x;
                    float gi = acc[0][ci] + xi;
                    float gf = acc[1][ci] + xff;
                    float gz = acc[2][ci] + xz;
                    float go = acc[3][ci] + xo;
                    float iv = sigmf(gi), fv = sigmf(gf), zv = tanhf(gz), ov = sigmf(go);
                    cst[ci] = fv * cst[ci] + iv * zv;
                    float h = ov * tanhf(cst[ci]);
                    pp += h * wo_c[ec];
                    hv[ec] = h;
                }
                union { __half h[2]; uint32_t u; } ph;
                ph.h[0] = __float2half(hv[0]);
                ph.h[1] = __float2half(hv[1]);
                *(uint32_t*)&g_hf[wb][row * Hn + j0 + cc0] = ph.u;
                part[er] = pp;
            }
            part[0] += __shfl_xor_sync(0xffffffffu, part[0], 1);
            part[0] += __shfl_xor_sync(0xffffffffu, part[0], 2);
            part[1] += __shfl_xor_sync(0xffffffffu, part[1], 1);
            part[1] += __shfl_xor_sync(0xffffffffu, part[1], 2);
            if (q == 0) {
                atomicAdd(&out[(size_t)r * Tn + t], part[0]);
                atomicAdd(&out[(size_t)(r + 8) * Tn + t], part[1]);
            }
        }

        // ---- grid barrier (128 CTAs, all resident) ----
        __threadfence();
        __syncthreads();
        if (tid == 0) {
            unsigned target = (unsigned)(t + 1);
            unsigned prev = atomicAdd(&g_count, 1u);
            if (prev == (unsigned)nblocks * target - 1u) {
                __threadfence();
                atomicExch(&g_gen, target);
            } else {
                while (*(volatile unsigned*)&g_gen < target) { __nanosleep(40); }
                __threadfence();
            }
        }
        __syncthreads();
    }
}

// =====================================================================
extern "C" void kernel_launch(void* const* d_in, const int* in_sizes, int n_in,
                              void* d_out, int out_size)
{
    const float* x    = (const float*)d_in[0];
    const float* Wih  = (const float*)d_in[1];
    const float* Whh  = (const float*)d_in[2];
    const float* bih  = (const float*)d_in[3];
    const float* bhh  = (const float*)d_in[4];
    const float* Wout = (const float*)d_in[5];
    const float* bout = (const float*)d_in[6];
    float* out = (float*)d_out;

    cudaFuncSetAttribute(xg_hmma, cudaFuncAttributeMaxDynamicSharedMemorySize, G_SMEM);
    cudaFuncSetAttribute(lstm_mma, cudaFuncAttributeMaxDynamicSharedMemorySize, SM_TOTAL2);

    init_kernel<<<256, 256>>>(out, bout);
    convert_kernel<<<(NXQ + NWQ + 255) / 256, 256>>>(x, Wih);
    xg_hmma<<<dim3(G4H / G_BN, Tn / G_BM, Bn), 256, G_SMEM>>>(bih, bhh);
    lstm_mma<<<128, 256, SM_TOTAL2>>>(Whh, Wout, out);
}

// round 16
// speedup vs baseline: 2.2558x; 1.0549x over previous
#include <cuda_runtime.h>
#include <cuda_bf16.h>
#include <cuda_fp16.h>
#include <cstdint>

// Problem constants
#define Bn   64
#define Dn   512
#define Tn   512
#define Hn   1024
#define G4H  4096

// ---------------- scratch (device globals; no allocation allowed) ----------------
__device__ float g_xg[(size_t)Bn * Tn * G4H];          // (B, T, 4H)
__device__ __align__(16) __half g_xh[(size_t)Bn * Dn * Tn];   // x fp16 (B, D, T)
__device__ __align__(16) __half g_wh[(size_t)G4H * Dn];       // W_ih fp16 (4H, D)
__device__ __align__(16) __half g_hf[2][Bn * Hn];      // h fp16, double-buffered by step
__device__ unsigned int g_count;
__device__ unsigned int g_gen;

// ---------------- helpers ----------------
__device__ __forceinline__ uint32_t smem_u32(const void* p) {
    uint32_t a;
    asm("{ .reg .u64 t; cvta.to.shared.u64 t, %1; cvt.u32.u64 %0, t; }" : "=r"(a) : "l"(p));
    return a;
}
__device__ __forceinline__ float sigmf(float x) { return 1.0f / (1.0f + expf(-x)); }

// warp-level HMMA fp16 (sm_80+ PTX: compiles on plain sm_103 target)
__device__ __forceinline__ void mma_f16(float* d, const uint32_t* a, const uint32_t* b) {
    asm volatile("mma.sync.aligned.m16n8k16.row.col.f32.f16.f16.f32 "
                 "{%0,%1,%2,%3}, {%4,%5,%6,%7}, {%8,%9}, {%0,%1,%2,%3};"
                 : "+f"(d[0]), "+f"(d[1]), "+f"(d[2]), "+f"(d[3])
                 : "r"(a[0]), "r"(a[1]), "r"(a[2]), "r"(a[3]), "r"(b[0]), "r"(b[1]));
}
__device__ __forceinline__ void ldsm4(uint32_t* r, uint32_t addr) {
    asm volatile("ldmatrix.sync.aligned.m8n8.x4.shared.b16 {%0,%1,%2,%3}, [%4];"
                 : "=r"(r[0]), "=r"(r[1]), "=r"(r[2]), "=r"(r[3]) : "r"(addr));
}
__device__ __forceinline__ void ldsm4t(uint32_t* r, uint32_t addr) {
    asm volatile("ldmatrix.sync.aligned.m8n8.x4.trans.shared.b16 {%0,%1,%2,%3}, [%4];"
                 : "=r"(r[0]), "=r"(r[1]), "=r"(r[2]), "=r"(r[3]) : "r"(addr));
}

// =====================================================================
// init: zero h(0), out = b_out, reset grid barrier
// =====================================================================
__global__ void init_kernel(float* __restrict__ out, const float* __restrict__ bout) {
    int i = blockIdx.x * blockDim.x + threadIdx.x;   // 0..65535
    if (i < 32768) {
        ((unsigned*)g_hf)[i] = 0u;
        out[i] = bout[0];
    }
    if (i == 0) { g_count = 0u; g_gen = 0u; }
}

// =====================================================================
// convert: x (B,D,T) fp32 -> g_xh fp16 ; W_ih (4H,D) fp32 -> g_wh fp16
// =====================================================================
#define NXQ ((Bn * Dn * Tn) / 4)      // 4194304
#define NWQ ((G4H * Dn) / 4)          // 524288
__global__ void convert_kernel(const float* __restrict__ x, const float* __restrict__ Wih) {
    int i = blockIdx.x * blockDim.x + threadIdx.x;
    if (i < NXQ) {
        float4 v = *(const float4*)&x[(size_t)i * 4];
        __half2 a = __floats2half2_rn(v.x, v.y);
        __half2 b = __floats2half2_rn(v.z, v.w);
        *(uint2*)&g_xh[(size_t)i * 4] = make_uint2(*(uint32_t*)&a, *(uint32_t*)&b);
    } else if (i < NXQ + NWQ) {
        int j = i - NXQ;
        float4 v = *(const float4*)&Wih[(size_t)j * 4];
        __half2 a = __floats2half2_rn(v.x, v.y);
        __half2 b = __floats2half2_rn(v.z, v.w);
        *(uint2*)&g_wh[(size_t)j * 4] = make_uint2(*(uint32_t*)&a, *(uint32_t*)&b);
    }
}

// =====================================================================
// Phase 1: xg = xh^T wh^T + biases.  HMMA fp16 GEMM (R14-proven, unchanged).
// =====================================================================
#define G_BM 128
#define G_BN 128
#define G_BK 64
#define G_APITCH 272
#define G_BPITCH 144
#define G_ASZ (G_BK * G_APITCH)
#define G_BSZ (G_BN * G_BPITCH)
#define G_SMEM (2 * (G_ASZ + G_BSZ))

__global__ __launch_bounds__(256, 1) void xg_hmma(
    const float* __restrict__ bih, const float* __restrict__ bhh)
{
    extern __shared__ char smem[];
    const uint32_t sb = smem_u32(smem);
    const int tid  = threadIdx.x;
    const int wid  = tid >> 5;
    const int lane = tid & 31;

    const int n0 = blockIdx.x * G_BN;
    const int t0 = blockIdx.y * G_BM;
    const int b  = blockIdx.z;

    const int mo = (wid & 3) * 32;
    const int no = (wid >> 2) * 64;

    const int krow = (lane & 7) + ((lane >> 4) & 1) * 8;
    const int mcol = ((lane >> 3) & 1) * 8;
    const int rowN  = (lane >> 4) * 8 + (lane & 7);
    const int koff8 = ((lane >> 3) & 1) * 8;

    const int arow = tid >> 4;
    const int acol8 = tid & 15;
    const int brow = tid >> 3;
    const int bcol8 = tid & 7;

    const __half* __restrict__ XH = g_xh + ((size_t)b * Dn) * Tn + t0;
    const __half* __restrict__ WH = g_wh + (size_t)n0 * Dn;

    float acc[2][8][4];
#pragma unroll
    for (int f = 0; f < 2; f++)
#pragma unroll
        for (int p = 0; p < 8; p++)
#pragma unroll
            for (int e = 0; e < 4; e++) acc[f][p][e] = 0.f;

    {
#pragma unroll
        for (int i = 0; i < 4; i++) {
            int kk = arow + i * 16;
            uint4 v = *(const uint4*)&XH[(size_t)kk * Tn + acol8 * 8];
            *(uint4*)(smem + 0 + kk * G_APITCH + acol8 * 16) = v;
        }
#pragma unroll
        for (int i = 0; i < 4; i++) {
            int nn = brow + i * 32;
            uint4 v = *(const uint4*)&WH[(size_t)nn * Dn + bcol8 * 8];
            *(uint4*)(smem + 2 * G_ASZ + nn * G_BPITCH + bcol8 * 16) = v;
        }
    }
    __syncthreads();

    const int NKT = Dn / G_BK;
#pragma unroll 1
    for (int kt = 0; kt < NKT; kt++) {
        uint4 pa[4], pb[4];
        if (kt < NKT - 1) {
            int k0 = (kt + 1) * G_BK;
#pragma unroll
            for (int i = 0; i < 4; i++) {
                int kk = arow + i * 16;
                pa[i] = *(const uint4*)&XH[(size_t)(k0 + kk) * Tn + acol8 * 8];
            }
#pragma unroll
            for (int i = 0; i < 4; i++) {
                int nn = brow + i * 32;
                pb[i] = *(const uint4*)&WH[(size_t)nn * Dn + k0 + bcol8 * 8];
            }
        }

        const uint32_t abuf = sb + (kt & 1) * G_ASZ;
        const uint32_t bbuf = sb + 2 * G_ASZ + (kt & 1) * G_BSZ;
#pragma unroll
        for (int s = 0; s < 4; s++) {
            uint32_t af[2][4];
#pragma unroll
            for (int f = 0; f < 2; f++)
                ldsm4t(af[f], abuf + (s * 16 + krow) * G_APITCH + (mo + f * 16 + mcol) * 2);
            uint32_t bf[8][2];
#pragma unroll
            for (int p = 0; p < 4; p++) {
                uint32_t rr[4];
                ldsm4(rr, bbuf + (no + p * 16 + rowN) * G_BPITCH + (s * 16 + koff8) * 2);
                bf[p * 2][0] = rr[0]; bf[p * 2][1] = rr[1];
                bf[p * 2 + 1][0] = rr[2]; bf[p * 2 + 1][1] = rr[3];
            }
#pragma unroll
            for (int f = 0; f < 2; f++)
#pragma unroll
                for (int p = 0; p < 8; p++)
                    mma_f16(acc[f][p], af[f], bf[p]);
        }

        if (kt < NKT - 1) {
            const uint32_t oa = (kt + 1) & 1;
            char* ab = smem + oa * G_ASZ;
            char* bb = smem + 2 * G_ASZ + oa * G_BSZ;
#pragma unroll
            for (int i = 0; i < 4; i++) {
                int kk = arow + i * 16;
                *(uint4*)(ab + kk * G_APITCH + acol8 * 16) = pa[i];
            }
#pragma unroll
            for (int i = 0; i < 4; i++) {
                int nn = brow + i * 32;
                *(uint4*)(bb + nn * G_BPITCH + bcol8 * 16) = pb[i];
            }
        }
        __syncthreads();
    }

    const int qq = lane & 3;
#pragma unroll
    for (int p = 0; p < 8; p++) {
        int n = n0 + no + (p >> 1) * 16 + (p & 1) * 8 + qq * 2;
        float2 bsv;
        bsv.x = bih[n] + bhh[n];
        bsv.y = bih[n + 1] + bhh[n + 1];
#pragma unroll
        for (int f = 0; f < 2; f++) {
            int r0 = t0 + mo + f * 16 + (lane >> 2);
            size_t base0 = ((size_t)b * Tn + r0) * G4H + n;
            size_t base1 = ((size_t)b * Tn + r0 + 8) * G4H + n;
            *(float2*)&g_xg[base0] = make_float2(acc[f][p][0] + bsv.x, acc[f][p][1] + bsv.y);
            *(float2*)&g_xg[base1] = make_float2(acc[f][p][2] + bsv.x, acc[f][p][3] + bsv.y);
        }
    }
}

// =====================================================================
// Phase 2: persistent HMMA recurrence, fp16, SPLIT-K across 8 warps.
// 128 CTAs x 256 thr. Warp = (m-tile = wid&3, K-half = wid>>2).
// All threads stage full h (64x1024 fp16) into one smem buffer per step.
// Split-K partials reduced via smem; epilogue in warps 0-3 (proven).
// =====================================================================
#define WPITCH 2064                    // 1032 fp16; 129x16B
#define SM_W   0
#define SM_H   66048                   // 32*2064
#define SM_RED (66048 + 64*2064)       // 198144
#define SM_TOTAL2 (198144 + 8192)      // 206336

__global__ __launch_bounds__(256, 1) void lstm_mma(
    const float* __restrict__ Whh,
    const float* __restrict__ Wout,
    float* __restrict__ out)
{
    extern __shared__ char smem[];
    const uint32_t sb = smem_u32(smem);
    const int tid  = threadIdx.x;
    const int wid  = tid >> 5;
    const int lane = tid & 31;
    const int j0   = blockIdx.x * 8;
    const int nblocks = gridDim.x;

    // ---- pack resident fp16 weights: w[n][k], n = g*8+cc ----
    for (int it = 0; it < 128; it++) {
        int idx = it * 256 + tid;           // 0..32767
        int n = idx >> 10, k = idx & 1023;
        int g = n >> 3, cc = n & 7;
        float w = Whh[(size_t)(g * Hn + j0 + cc) * Hn + k];
        *(__half*)(smem + SM_W + n * WPITCH + k * 2) = __float2half(w);
    }
    __syncthreads();

    // warp geometry: m-tile and K-half
    const int mw  = wid & 3;                 // m tile: rows mw*16..mw*16+15
    const int kh  = wid >> 2;                // K half: k in [kh*512, kh*512+512)
    const int r   = mw * 16 + (lane >> 2);   // D rows r, r+8
    const int q   = lane & 3;
    const int cc0 = q * 2;
    // A ldmatrix address pieces
    const int am   = lane >> 3;
    const int arow = (lane & 7) + (am & 1) * 8;
    const int acol = (am >> 1) * 8;
    // B ldsm4 (gate-paired)
    const int rowW  = (lane >> 4) * 8 + (lane & 7);
    const int koff8 = ((lane >> 3) & 1) * 8;
    const uint32_t b01 = sb + SM_W + rowW * WPITCH + (kh * 512 + koff8) * 2;  // gates 0,1
    const uint32_t b23 = b01 + 16 * WPITCH;                                   // gates 2,3
    const uint32_t abase = sb + SM_H + (mw * 16 + arow) * WPITCH + (kh * 512 + acol) * 2;
    // reduction slots: 16 floats per (wid&3, lane), laid out [j][lane] contiguous per j
    const uint32_t red_my = sb + SM_RED + (mw * 16) * 128 + lane * 4;

    float wo_c[2];
    wo_c[0] = Wout[j0 + cc0];
    wo_c[1] = Wout[j0 + cc0 + 1];

    float cst[4] = {0.f, 0.f, 0.f, 0.f};

    for (int t = 0; t < Tn; t++) {
        const int rb = t & 1, wb = rb ^ 1;

        float2 xf[2][4];
        if (wid < 4) {
            // xg prefetch (independent LDGs, consumed in epilogue)
#pragma unroll
            for (int er = 0; er < 2; er++) {
                size_t base = ((size_t)(r + er * 8) * Tn + t) * G4H + j0 + cc0;
#pragma unroll
                for (int g = 0; g < 4; g++)
                    xf[er][g] = *(const float2*)&g_xg[base + (size_t)g * Hn];
            }
        }

        // ---- all threads stage full h: 64 rows x 1024 fp16 ----
        {
#pragma unroll
            for (int i = 0; i < 32; i++) {
                int id = i * 256 + tid;          // 0..8191
                int row = id >> 7, qq = id & 127;
                *(uint4*)(smem + SM_H + row * WPITCH + qq * 16) =
                    *(const uint4*)&g_hf[rb][row * Hn + qq * 8];
            }
        }
        __syncthreads();

        // ---- mma: 32 k-steps over this warp's K half ----
        float acc[4][4];
#pragma unroll
        for (int g = 0; g < 4; g++)
#pragma unroll
            for (int p = 0; p < 4; p++) acc[g][p] = 0.f;

#pragma unroll
        for (int ks = 0; ks < 32; ks++) {
            uint32_t a[4];
            ldsm4(a, abase + ks * 32);
            uint32_t bf[4][2];
            {
                uint32_t rr[4];
                ldsm4(rr, b01 + ks * 32);
                bf[0][0] = rr[0]; bf[0][1] = rr[1];
                bf[1][0] = rr[2]; bf[1][1] = rr[3];
                ldsm4(rr, b23 + ks * 32);
                bf[2][0] = rr[0]; bf[2][1] = rr[1];
                bf[3][0] = rr[2]; bf[3][1] = rr[3];
            }
#pragma unroll
            for (int g = 0; g < 4; g++)
                mma_f16(acc[g], a, bf[g]);
        }
        __syncthreads();

        // ---- split-K reduction: warps 4-7 publish partials ----
        if (wid >= 4) {
#pragma unroll
            for (int g = 0; g < 4; g++)
#pragma unroll
                for (int p = 0; p < 4; p++)
                    *(float*)(smem + (red_my - sb) + (g * 4 + p) * 128) = acc[g][p];
        }
        __syncthreads();

        // ---- epilogue (warps 0-3) ----
        if (wid < 4) {
#pragma unroll
            for (int g = 0; g < 4; g++)
#pragma unroll
                for (int p = 0; p < 4; p++)
                    acc[g][p] += *(const float*)(smem + (red_my - sb) + (g * 4 + p) * 128);

            float part[2];
#pragma unroll
            for (int er = 0; er < 2; er++) {
                int row = r + er * 8;
                float hv[2], pp = 0.f;
#pragma unroll
                for (int ec = 0; ec < 2; ec++) {
                    int ci = er * 2 + ec;
                    float xi = ec ? xf[er][0].y : xf[er][0].x;
                    float xff = ec ? xf[er][1].y : xf[er][1].x;
                    float xz = ec ? xf[er][2].y : xf[er][2].x;
                    float xo = ec ? xf[er][3].y : xf[er][3].x;
                    float gi = acc[0][ci] + xi;
                    float gf = acc[1][ci] + xff;
                    float gz = acc[2][ci] + xz;
                    float go = acc[3][ci] + xo;
                    float iv = sigmf(gi), fv = sigmf(gf), zv = tanhf(gz), ov = sigmf(go);
                    cst[ci] = fv * cst[ci] + iv * zv;
                    float h = ov * tanhf(cst[ci]);
                    pp += h * wo_c[ec];
                    hv[ec] = h;
                }
                union { __half h[2]; uint32_t u; } ph;
                ph.h[0] = __float2half(hv[0]);
                ph.h[1] = __float2half(hv[1]);
                *(uint32_t*)&g_hf[wb][row * Hn + j0 + cc0] = ph.u;
                part[er] = pp;
            }
            part[0] += __shfl_xor_sync(0xffffffffu, part[0], 1);
            part[0] += __shfl_xor_sync(0xffffffffu, part[0], 2);
            part[1] += __shfl_xor_sync(0xffffffffu, part[1], 1);
            part[1] += __shfl_xor_sync(0xffffffffu, part[1], 2);
            if (q == 0) {
                atomicAdd(&out[(size_t)r * Tn + t], part[0]);
                atomicAdd(&out[(size_t)(r + 8) * Tn + t], part[1]);
            }
        }

        // ---- grid barrier (128 CTAs, all resident) ----
        __threadfence();
        __syncthreads();
        if (tid == 0) {
            unsigned target = (unsigned)(t + 1);
            unsigned prev = atomicAdd(&g_count, 1u);
            if (prev == (unsigned)nblocks * target - 1u) {
                __threadfence();
                atomicExch(&g_gen, target);
            } else {
                while (*(volatile unsigned*)&g_gen < target) { __nanosleep(40); }
                __threadfence();
            }
        }
        __syncthreads();
    }
}

// =====================================================================
extern "C" void kernel_launch(void* const* d_in, const int* in_sizes, int n_in,
                              void* d_out, int out_size)
{
    const float* x    = (const float*)d_in[0];
    const float* Wih  = (const float*)d_in[1];
    const float* Whh  = (const float*)d_in[2];
    const float* bih  = (const float*)d_in[3];
    const float* bhh  = (const float*)d_in[4];
    const float* Wout = (const float*)d_in[5];
    const float* bout = (const float*)d_in[6];
    float* out = (float*)d_out;

    cudaFuncSetAttribute(xg_hmma, cudaFuncAttributeMaxDynamicSharedMemorySize, G_SMEM);
    cudaFuncSetAttribute(lstm_mma, cudaFuncAttributeMaxDynamicSharedMemorySize, SM_TOTAL2);

    init_kernel<<<256, 256>>>(out, bout);
    convert_kernel<<<(NXQ + NWQ + 255) / 256, 256>>>(x, Wih);
    xg_hmma<<<dim3(G4H / G_BN, Tn / G_BM, Bn), 256, G_SMEM>>>(bih, bhh);
    lstm_mma<<<128, 256, SM_TOTAL2>>>(Whh, Wout, out);
}

// round 17
// speedup vs baseline: 2.3089x; 1.0236x over previous
#include <cuda_runtime.h>
#include <cuda_bf16.h>
#include <cuda_fp16.h>
#include <cstdint>

// Problem constants
#define Bn   64
#define Dn   512
#define Tn   512
#define Hn   1024
#define G4H  4096

// ---------------- scratch (device globals; no allocation allowed) ----------------
__device__ float g_xg[(size_t)Bn * Tn * G4H];          // (B, T, 4H)
__device__ __align__(16) __half g_xh[(size_t)Bn * Dn * Tn];   // x fp16 (B, D, T)
__device__ __align__(16) __half g_wh[(size_t)G4H * Dn];       // W_ih fp16 (4H, D)
__device__ __align__(16) __half g_hf[2][Bn * Hn];      // h fp16, double-buffered by step
__device__ unsigned int g_count;
__device__ unsigned int g_gen;

// ---------------- helpers ----------------
__device__ __forceinline__ uint32_t smem_u32(const void* p) {
    uint32_t a;
    asm("{ .reg .u64 t; cvta.to.shared.u64 t, %1; cvt.u32.u64 %0, t; }" : "=r"(a) : "l"(p));
    return a;
}
__device__ __forceinline__ float sigmf(float x) { return 1.0f / (1.0f + expf(-x)); }

// warp-level HMMA fp16 (sm_80+ PTX: compiles on plain sm_103 target)
__device__ __forceinline__ void mma_f16(float* d, const uint32_t* a, const uint32_t* b) {
    asm volatile("mma.sync.aligned.m16n8k16.row.col.f32.f16.f16.f32 "
                 "{%0,%1,%2,%3}, {%4,%5,%6,%7}, {%8,%9}, {%0,%1,%2,%3};"
                 : "+f"(d[0]), "+f"(d[1]), "+f"(d[2]), "+f"(d[3])
                 : "r"(a[0]), "r"(a[1]), "r"(a[2]), "r"(a[3]), "r"(b[0]), "r"(b[1]));
}
__device__ __forceinline__ void ldsm4(uint32_t* r, uint32_t addr) {
    asm volatile("ldmatrix.sync.aligned.m8n8.x4.shared.b16 {%0,%1,%2,%3}, [%4];"
                 : "=r"(r[0]), "=r"(r[1]), "=r"(r[2]), "=r"(r[3]) : "r"(addr));
}
__device__ __forceinline__ void ldsm4t(uint32_t* r, uint32_t addr) {
    asm volatile("ldmatrix.sync.aligned.m8n8.x4.trans.shared.b16 {%0,%1,%2,%3}, [%4];"
                 : "=r"(r[0]), "=r"(r[1]), "=r"(r[2]), "=r"(r[3]) : "r"(addr));
}
// cp.async 16B global->shared (sm_80+)
#define CPA16(sm, gp) asm volatile("cp.async.cg.shared.global [%0], [%1], 16;" :: "r"(sm), "l"(gp) : "memory")
#define CPA_COMMIT()  asm volatile("cp.async.commit_group;" ::: "memory")
#define CPA_WAIT0()   asm volatile("cp.async.wait_group 0;" ::: "memory")

// =====================================================================
// init: zero h(0), out = b_out, reset grid barrier
// =====================================================================
__global__ void init_kernel(float* __restrict__ out, const float* __restrict__ bout) {
    int i = blockIdx.x * blockDim.x + threadIdx.x;   // 0..65535
    if (i < 32768) {
        ((unsigned*)g_hf)[i] = 0u;
        out[i] = bout[0];
    }
    if (i == 0) { g_count = 0u; g_gen = 0u; }
}

// =====================================================================
// convert: x (B,D,T) fp32 -> g_xh fp16 ; W_ih (4H,D) fp32 -> g_wh fp16
// =====================================================================
#define NXQ ((Bn * Dn * Tn) / 4)      // 4194304
#define NWQ ((G4H * Dn) / 4)          // 524288
__global__ void convert_kernel(const float* __restrict__ x, const float* __restrict__ Wih) {
    int i = blockIdx.x * blockDim.x + threadIdx.x;
    if (i < NXQ) {
        float4 v = *(const float4*)&x[(size_t)i * 4];
        __half2 a = __floats2half2_rn(v.x, v.y);
        __half2 b = __floats2half2_rn(v.z, v.w);
        *(uint2*)&g_xh[(size_t)i * 4] = make_uint2(*(uint32_t*)&a, *(uint32_t*)&b);
    } else if (i < NXQ + NWQ) {
        int j = i - NXQ;
        float4 v = *(const float4*)&Wih[(size_t)j * 4];
        __half2 a = __floats2half2_rn(v.x, v.y);
        __half2 b = __floats2half2_rn(v.z, v.w);
        *(uint2*)&g_wh[(size_t)j * 4] = make_uint2(*(uint32_t*)&a, *(uint32_t*)&b);
    }
}

// =====================================================================
// Phase 1: xg = xh^T wh^T + biases.  HMMA fp16 GEMM (R14-proven, unchanged).
// =====================================================================
#define G_BM 128
#define G_BN 128
#define G_BK 64
#define G_APITCH 272
#define G_BPITCH 144
#define G_ASZ (G_BK * G_APITCH)
#define G_BSZ (G_BN * G_BPITCH)
#define G_SMEM (2 * (G_ASZ + G_BSZ))

__global__ __launch_bounds__(256, 1) void xg_hmma(
    const float* __restrict__ bih, const float* __restrict__ bhh)
{
    extern __shared__ char smem[];
    const uint32_t sb = smem_u32(smem);
    const int tid  = threadIdx.x;
    const int wid  = tid >> 5;
    const int lane = tid & 31;

    const int n0 = blockIdx.x * G_BN;
    const int t0 = blockIdx.y * G_BM;
    const int b  = blockIdx.z;

    const int mo = (wid & 3) * 32;
    const int no = (wid >> 2) * 64;

    const int krow = (lane & 7) + ((lane >> 4) & 1) * 8;
    const int mcol = ((lane >> 3) & 1) * 8;
    const int rowN  = (lane >> 4) * 8 + (lane & 7);
    const int koff8 = ((lane >> 3) & 1) * 8;

    const int arow = tid >> 4;
    const int acol8 = tid & 15;
    const int brow = tid >> 3;
    const int bcol8 = tid & 7;

    const __half* __restrict__ XH = g_xh + ((size_t)b * Dn) * Tn + t0;
    const __half* __restrict__ WH = g_wh + (size_t)n0 * Dn;

    float acc[2][8][4];
#pragma unroll
    for (int f = 0; f < 2; f++)
#pragma unroll
        for (int p = 0; p < 8; p++)
#pragma unroll
            for (int e = 0; e < 4; e++) acc[f][p][e] = 0.f;

    {
#pragma unroll
        for (int i = 0; i < 4; i++) {
            int kk = arow + i * 16;
            uint4 v = *(const uint4*)&XH[(size_t)kk * Tn + acol8 * 8];
            *(uint4*)(smem + 0 + kk * G_APITCH + acol8 * 16) = v;
        }
#pragma unroll
        for (int i = 0; i < 4; i++) {
            int nn = brow + i * 32;
            uint4 v = *(const uint4*)&WH[(size_t)nn * Dn + bcol8 * 8];
            *(uint4*)(smem + 2 * G_ASZ + nn * G_BPITCH + bcol8 * 16) = v;
        }
    }
    __syncthreads();

    const int NKT = Dn / G_BK;
#pragma unroll 1
    for (int kt = 0; kt < NKT; kt++) {
        uint4 pa[4], pb[4];
        if (kt < NKT - 1) {
            int k0 = (kt + 1) * G_BK;
#pragma unroll
            for (int i = 0; i < 4; i++) {
                int kk = arow + i * 16;
                pa[i] = *(const uint4*)&XH[(size_t)(k0 + kk) * Tn + acol8 * 8];
            }
#pragma unroll
            for (int i = 0; i < 4; i++) {
                int nn = brow + i * 32;
                pb[i] = *(const uint4*)&WH[(size_t)nn * Dn + k0 + bcol8 * 8];
            }
        }

        const uint32_t abuf = sb + (kt & 1) * G_ASZ;
        const uint32_t bbuf = sb + 2 * G_ASZ + (kt & 1) * G_BSZ;
#pragma unroll
        for (int s = 0; s < 4; s++) {
            uint32_t af[2][4];
#pragma unroll
            for (int f = 0; f < 2; f++)
                ldsm4t(af[f], abuf + (s * 16 + krow) * G_APITCH + (mo + f * 16 + mcol) * 2);
            uint32_t bf[8][2];
#pragma unroll
            for (int p = 0; p < 4; p++) {
                uint32_t rr[4];
                ldsm4(rr, bbuf + (no + p * 16 + rowN) * G_BPITCH + (s * 16 + koff8) * 2);
                bf[p * 2][0] = rr[0]; bf[p * 2][1] = rr[1];
                bf[p * 2 + 1][0] = rr[2]; bf[p * 2 + 1][1] = rr[3];
            }
#pragma unroll
            for (int f = 0; f < 2; f++)
#pragma unroll
                for (int p = 0; p < 8; p++)
                    mma_f16(acc[f][p], af[f], bf[p]);
        }

        if (kt < NKT - 1) {
            const uint32_t oa = (kt + 1) & 1;
            char* ab = smem + oa * G_ASZ;
            char* bb = smem + 2 * G_ASZ + oa * G_BSZ;
#pragma unroll
            for (int i = 0; i < 4; i++) {
                int kk = arow + i * 16;
                *(uint4*)(ab + kk * G_APITCH + acol8 * 16) = pa[i];
            }
#pragma unroll
            for (int i = 0; i < 4; i++) {
                int nn = brow + i * 32;
                *(uint4*)(bb + nn * G_BPITCH + bcol8 * 16) = pb[i];
            }
        }
        __syncthreads();
    }

    const int qq = lane & 3;
#pragma unroll
    for (int p = 0; p < 8; p++) {
        int n = n0 + no + (p >> 1) * 16 + (p & 1) * 8 + qq * 2;
        float2 bsv;
        bsv.x = bih[n] + bhh[n];
        bsv.y = bih[n + 1] + bhh[n + 1];
#pragma unroll
        for (int f = 0; f < 2; f++) {
            int r0 = t0 + mo + f * 16 + (lane >> 2);
            size_t base0 = ((size_t)b * Tn + r0) * G4H + n;
            size_t base1 = ((size_t)b * Tn + r0 + 8) * G4H + n;
            *(float2*)&g_xg[base0] = make_float2(acc[f][p][0] + bsv.x, acc[f][p][1] + bsv.y);
            *(float2*)&g_xg[base1] = make_float2(acc[f][p][2] + bsv.x, acc[f][p][3] + bsv.y);
        }
    }
}

// =====================================================================
// Phase 2: persistent HMMA recurrence, fp16, SPLIT-K across 8 warps.
// 128 CTAs x 256 thr. Warp = (m-tile = wid&3, K-half = wid>>2).
// h staged via cp.async into one smem buffer per step.
// Grid barrier: red.release arrivals + ld.acquire poll (no serialized ATOMG).
// =====================================================================
#define WPITCH 2064                    // 1032 fp16; 129x16B
#define SM_W   0
#define SM_H   66048                   // 32*2064
#define SM_RED (66048 + 64*2064)       // 198144
#define SM_TOTAL2 (198144 + 8192)      // 206336

__global__ __launch_bounds__(256, 1) void lstm_mma(
    const float* __restrict__ Whh,
    const float* __restrict__ Wout,
    float* __restrict__ out)
{
    extern __shared__ char smem[];
    const uint32_t sb = smem_u32(smem);
    const int tid  = threadIdx.x;
    const int wid  = tid >> 5;
    const int lane = tid & 31;
    const int j0   = blockIdx.x * 8;
    const unsigned nblocks = gridDim.x;

    // ---- pack resident fp16 weights: w[n][k], n = g*8+cc ----
    for (int it = 0; it < 128; it++) {
        int idx = it * 256 + tid;           // 0..32767
        int n = idx >> 10, k = idx & 1023;
        int g = n >> 3, cc = n & 7;
        float w = Whh[(size_t)(g * Hn + j0 + cc) * Hn + k];
        *(__half*)(smem + SM_W + n * WPITCH + k * 2) = __float2half(w);
    }
    __syncthreads();

    // warp geometry: m-tile and K-half
    const int mw  = wid & 3;                 // m tile: rows mw*16..mw*16+15
    const int kh  = wid >> 2;                // K half: k in [kh*512, kh*512+512)
    const int r   = mw * 16 + (lane >> 2);   // D rows r, r+8
    const int q   = lane & 3;
    const int cc0 = q * 2;
    // A ldmatrix address pieces
    const int am   = lane >> 3;
    const int arow = (lane & 7) + (am & 1) * 8;
    const int acol = (am >> 1) * 8;
    // B ldsm4 (gate-paired)
    const int rowW  = (lane >> 4) * 8 + (lane & 7);
    const int koff8 = ((lane >> 3) & 1) * 8;
    const uint32_t b01 = sb + SM_W + rowW * WPITCH + (kh * 512 + koff8) * 2;  // gates 0,1
    const uint32_t b23 = b01 + 16 * WPITCH;                                   // gates 2,3
    const uint32_t abase = sb + SM_H + (mw * 16 + arow) * WPITCH + (kh * 512 + acol) * 2;
    // reduction slots
    const uint32_t red_my = sb + SM_RED + (mw * 16) * 128 + lane * 4;
    // staging addresses (fixed per thread): 32 x 16B per thread
    const int srow = tid >> 3;               // 0..31 base rows (x2 groups of 32)
    const int sq   = tid & 7;

    float wo_c[2];
    wo_c[0] = Wout[j0 + cc0];
    wo_c[1] = Wout[j0 + cc0 + 1];

    float cst[4] = {0.f, 0.f, 0.f, 0.f};

    for (int t = 0; t < Tn; t++) {
        const int rb = t & 1, wb = rb ^ 1;

        // ---- stage full h via cp.async: 64 rows x 1024 fp16 = 8192 x 16B ----
        {
#pragma unroll
            for (int i = 0; i < 32; i++) {
                int id = i * 256 + tid;          // 0..8191
                int row = id >> 7, qq = id & 127;
                CPA16(sb + SM_H + row * WPITCH + qq * 16,
                      (const char*)&g_hf[rb][row * Hn + qq * 8]);
            }
            CPA_COMMIT();
        }

        // xg prefetch overlaps with cp.async completion
        float2 xf[2][4];
        if (wid < 4) {
#pragma unroll
            for (int er = 0; er < 2; er++) {
                size_t base = ((size_t)(r + er * 8) * Tn + t) * G4H + j0 + cc0;
#pragma unroll
                for (int g = 0; g < 4; g++)
                    xf[er][g] = *(const float2*)&g_xg[base + (size_t)g * Hn];
            }
        }

        CPA_WAIT0();
        __syncthreads();

        // ---- mma: 32 k-steps over this warp's K half ----
        float acc[4][4];
#pragma unroll
        for (int g = 0; g < 4; g++)
#pragma unroll
            for (int p = 0; p < 4; p++) acc[g][p] = 0.f;

#pragma unroll
        for (int ks = 0; ks < 32; ks++) {
            uint32_t a[4];
            ldsm4(a, abase + ks * 32);
            uint32_t bf[4][2];
            {
                uint32_t rr[4];
                ldsm4(rr, b01 + ks * 32);
                bf[0][0] = rr[0]; bf[0][1] = rr[1];
                bf[1][0] = rr[2]; bf[1][1] = rr[3];
                ldsm4(rr, b23 + ks * 32);
                bf[2][0] = rr[0]; bf[2][1] = rr[1];
                bf[3][0] = rr[2]; bf[3][1] = rr[3];
            }
#pragma unroll
            for (int g = 0; g < 4; g++)
                mma_f16(acc[g], a, bf[g]);
        }
        __syncthreads();

        // ---- split-K reduction: warps 4-7 publish partials ----
        if (wid >= 4) {
#pragma unroll
            for (int g = 0; g < 4; g++)
#pragma unroll
                for (int p = 0; p < 4; p++)
                    *(float*)(smem + (red_my - sb) + (g * 4 + p) * 128) = acc[g][p];
        }
        __syncthreads();

        // ---- epilogue (warps 0-3) ----
        if (wid < 4) {
#pragma unroll
            for (int g = 0; g < 4; g++)
#pragma unroll
                for (int p = 0; p < 4; p++)
                    acc[g][p] += *(const float*)(smem + (red_my - sb) + (g * 4 + p) * 128);

            float part[2];
#pragma unroll
            for (int er = 0; er < 2; er++) {
                int row = r + er * 8;
                float hv[2], pp = 0.f;
#pragma unroll
                for (int ec = 0; ec < 2; ec++) {
                    int ci = er * 2 + ec;
                    float xi = ec ? xf[er][0].y : xf[er][0].x;
                    float xff = ec ? xf[er][1].y : xf[er][1].x;
                    float xz = ec ? xf[er][2].y : xf[er][2].x;
                    float xo = ec ? xf[er][3].y : xf[er][3].x;
                    float gi = acc[0][ci] + xi;
                    float gf = acc[1][ci] + xff;
                    float gz = acc[2][ci] + xz;
                    float go = acc[3][ci] + xo;
                    float iv = sigmf(gi), fv = sigmf(gf), zv = tanhf(gz), ov = sigmf(go);
                    cst[ci] = fv * cst[ci] + iv * zv;
                    float h = ov * tanhf(cst[ci]);
                    pp += h * wo_c[ec];
                    hv[ec] = h;
                }
                union { __half h[2]; uint32_t u; } ph;
                ph.h[0] = __float2half(hv[0]);
                ph.h[1] = __float2half(hv[1]);
                *(uint32_t*)&g_hf[wb][row * Hn + j0 + cc0] = ph.u;
                part[er] = pp;
            }
            part[0] += __shfl_xor_sync(0xffffffffu, part[0], 1);
            part[0] += __shfl_xor_sync(0xffffffffu, part[0], 2);
            part[1] += __shfl_xor_sync(0xffffffffu, part[1], 1);
            part[1] += __shfl_xor_sync(0xffffffffu, part[1], 2);
            if (q == 0) {
                atomicAdd(&out[(size_t)r * Tn + t], part[0]);
                atomicAdd(&out[(size_t)(r + 8) * Tn + t], part[1]);
            }
        }

        // ---- grid barrier: REDG release arrival + acquire-poll (all resident) ----
        __threadfence();
        __syncthreads();
        if (tid == 0) {
            asm volatile("red.release.gpu.global.add.u32 [%0], %1;"
                         :: "l"(&g_count), "r"(1u) : "memory");
            unsigned target = nblocks * (unsigned)(t + 1);
            unsigned c;
            do {
                asm volatile("ld.acquire.gpu.global.u32 %0, [%1];"
                             : "=r"(c) : "l"(&g_count));
            } while (c < target);
        }
        __syncthreads();
    }
}

// =====================================================================
extern "C" void kernel_launch(void* const* d_in, const int* in_sizes, int n_in,
                              void* d_out, int out_size)
{
    const float* x    = (const float*)d_in[0];
    const float* Wih  = (const float*)d_in[1];
    const float* Whh  = (const float*)d_in[2];
    const float* bih  = (const float*)d_in[3];
    const float* bhh  = (const float*)d_in[4];
    const float* Wout = (const float*)d_in[5];
    const float* bout = (const float*)d_in[6];
    float* out = (float*)d_out;

    cudaFuncSetAttribute(xg_hmma, cudaFuncAttributeMaxDynamicSharedMemorySize, G_SMEM);
    cudaFuncSetAttribute(lstm_mma, cudaFuncAttributeMaxDynamicSharedMemorySize, SM_TOTAL2);

    init_kernel<<<256, 256>>>(out, bout);
    convert_kernel<<<(NXQ + NWQ + 255) / 256, 256>>>(x, Wih);
    xg_hmma<<<dim3(G4H / G_BN, Tn / G_BM, Bn), 256, G_SMEM>>>(bih, bhh);
    lstm_mma<<<128, 256, SM_TOTAL2>>>(Whh, Wout, out);
}